// round 15
// baseline (speedup 1.0000x reference)
#include <cuda_runtime.h>
#include <cuda_bf16.h>
#include <math.h>
#include <stdint.h>

// ---------------- problem constants ----------------
#define BB       16384
#define MEMD     128
#define TIMED    100
#define MAXNODES 1100000

// ---------------- device scratch ----------------
__device__ float g_ut[BB * MEMD];
__device__ float g_it[BB * MEMD];
__device__ int   g_win[MAXNODES];
// pre-split bf16 weight pools, [128, Kp] K-major per weight, concatenated
#define POOL_ELE (2048 * 128)
__device__ __align__(16) __nv_bfloat16 g_wph[POOL_ELE];
__device__ __align__(16) __nv_bfloat16 g_wpl[POOL_ELE];
#define PB_U1 0
#define PB_I1 65536
#define PB_U2 131072
#define PB_I2 147456
#define PB_P1 163840
#define PB_P2 180224
#define PB_T1 196608
#define PB_O  229376

// ---------------- helpers ----------------
__device__ __forceinline__ uint32_t smem_u32(const void* p) {
    uint32_t a;
    asm("{ .reg .u64 t; cvta.to.shared.u64 t, %1; cvt.u32.u64 %0, t; }" : "=r"(a) : "l"(p));
    return a;
}
__device__ __forceinline__ void ldm_x4(uint32_t* r, uint32_t addr) {
    asm volatile("ldmatrix.sync.aligned.m8n8.x4.shared.b16 {%0,%1,%2,%3}, [%4];"
        : "=r"(r[0]), "=r"(r[1]), "=r"(r[2]), "=r"(r[3]) : "r"(addr));
}
__device__ __forceinline__ void mma_bf16(float* c, const uint32_t* a, const uint32_t* b) {
    asm volatile("mma.sync.aligned.m16n8k16.row.col.f32.bf16.bf16.f32 "
        "{%0,%1,%2,%3}, {%4,%5,%6,%7}, {%8,%9}, {%0,%1,%2,%3};"
        : "+f"(c[0]), "+f"(c[1]), "+f"(c[2]), "+f"(c[3])
        : "r"(a[0]), "r"(a[1]), "r"(a[2]), "r"(a[3]), "r"(b[0]), "r"(b[1]));
}
__device__ __forceinline__ void cp16(uint32_t smaddr, const void* g) {
    asm volatile("cp.async.ca.shared.global [%0], [%1], 16;" :: "r"(smaddr), "l"(g));
}
__device__ __forceinline__ void split2(float v0, float v1, uint32_t& hi, uint32_t& lo) {
    __nv_bfloat16 h0 = __float2bfloat16(v0);
    __nv_bfloat16 h1 = __float2bfloat16(v1);
    __nv_bfloat16 l0 = __float2bfloat16(v0 - __bfloat162float(h0));
    __nv_bfloat16 l1 = __float2bfloat16(v1 - __bfloat162float(h1));
    __nv_bfloat162 H = __halves2bfloat162(h0, h1);
    __nv_bfloat162 L = __halves2bfloat162(l0, l1);
    hi = *(uint32_t*)&H; lo = *(uint32_t*)&L;
}

// ---------------- fused weight prep ----------------
struct PrepArgs {
    const float* W[8];
    int K[8];
    int Kp[8];
    int base[8];
    int cum[9];
};
__global__ void prep_all_kernel(PrepArgs pa)
{
    int kglob = blockIdx.x;
    int n = threadIdx.x;
    int w = 0;
    #pragma unroll
    for (int i = 0; i < 8; i++) if (kglob >= pa.cum[i + 1]) w = i + 1;
    int k = kglob - pa.cum[w];
    float v = (k < pa.K[w]) ? pa.W[w][(size_t)k * 128 + n] : 0.f;
    __nv_bfloat16 hi = __float2bfloat16(v);
    __nv_bfloat16 lo = __float2bfloat16(v - __bfloat162float(hi));
    int Kp = pa.Kp[w];
    g_wph[pa.base[w] + (size_t)n * Kp + k] = hi;
    g_wpl[pa.base[w] + (size_t)n * Kp + k] = lo;
}

// ---------------- fused chain kernel ----------------
struct ChainArgs {
    const int* ida;
    const int* idb;
    const float* emb;
    int wbase[6];
    int kp[6];
    const float* bias[6];
    float* ut;
    float* outp;
};

#define MROWS 64
#define ACT_STR 136
#define CH_STR  72
// bf16-element offsets. CHA aliases the head of ACT (dead when CHA is live).
#define OFF_ACT_H 0
#define OFF_ACT_L (MROWS*ACT_STR)
#define OFF_CHA_H 0
#define OFF_CHA_L (MROWS*CH_STR)
#define OFF_CHW0  (2*MROWS*ACT_STR)
#define CHW_BUF   (2*128*CH_STR)
#define OFF_CHW1  (OFF_CHW0 + CHW_BUF)
#define SMEM_ELE  (OFF_CHW1 + CHW_BUF)   // 54272 ele = 108.5KB (caps at 2 CTA/SM)

// __maxnreg__(112): 512x112 = 57344 regs -> exactly 8192 regs/SM free for one
// 256-thread x 32-reg copy CTA to co-schedule.
__global__ void __maxnreg__(112)
chain_kernel(ChainArgs au, ChainArgs ai,
             const float* __restrict__ memory,
             const float* __restrict__ edge,
             const float* __restrict__ ts,
             const float* __restrict__ tw,
             const float* __restrict__ tb)
{
    extern __shared__ __nv_bfloat16 sm[];
    __nv_bfloat16* ACT_H = sm + OFF_ACT_H;
    __nv_bfloat16* ACT_L = sm + OFF_ACT_L;
    __nv_bfloat16* CHA_H = sm + OFF_CHA_H;
    __nv_bfloat16* CHA_L = sm + OFF_CHA_L;

    __shared__ int   ida_s[MROWS], idb_s[MROWS];
    __shared__ float ts_s[MROWS], tw_s[TIMED], tb_s[TIMED];

    const ChainArgs P = blockIdx.y ? ai : au;
    const int tid  = threadIdx.x;
    const int lane = tid & 31;
    const int wid  = tid >> 5;
    const int wm   = (wid & 3) * 16;
    const int wn   = (wid >> 2) * 64;
    const int brow = blockIdx.x * MROWS;

    if (tid < MROWS) {
        ida_s[tid] = P.ida[brow + tid];
        idb_s[tid] = P.idb[brow + tid];
        ts_s[tid]  = ts[brow + tid];
    }
    if (tid >= 128 && tid < 128 + TIMED) {
        tw_s[tid - 128] = tw[tid - 128];
        tb_s[tid - 128] = tb[tid - 128];
    }
    __syncthreads();

    const int arow  = (lane & 7) + ((lane >> 3) & 1) * 8;
    const int akoff = (lane >> 4) * 8;
    const int brw2  = ((lane >> 4) << 3) + (lane & 7);
    const int bkoff = ((lane >> 3) & 1) * 8;
    const int g = lane >> 2, q = lane & 3;

    const int rl[6] = {1, 0, 1, 0, 1, 0};

    // prologue: prefetch W chunk (s=0, kb=0) into buffer 0
    {
        const __nv_bfloat16* WH = g_wph + P.wbase[0];
        const __nv_bfloat16* WL = g_wpl + P.wbase[0];
        const int Kp0 = P.kp[0];
        __nv_bfloat16* DH = sm + OFF_CHW0;
        __nv_bfloat16* DL = DH + 128 * CH_STR;
        for (int idx = tid; idx < 1024; idx += 256) {
            int n = idx >> 3, seg = idx & 7;
            uint32_t so = n * CH_STR + seg * 8;
            cp16(smem_u32(DH + so), WH + (size_t)n * Kp0 + seg * 8);
            cp16(smem_u32(DL + so), WL + (size_t)n * Kp0 + seg * 8);
        }
        asm volatile("cp.async.commit_group;" ::: "memory");
    }

    int fg = 0;

    for (int s = 0; s < 6; s++) {
        const int Kp = P.kp[s];
        float acc[8][4];
        #pragma unroll
        for (int j = 0; j < 8; j++)
            #pragma unroll
            for (int k = 0; k < 4; k++) acc[j][k] = 0.f;

        const int nch = Kp >> 6;
        for (int c = 0; c < nch; c++, fg++) {
            const int kb = c << 6;
            const bool fromAct = (s > 0) && (kb < 128);

            // prefetch NEXT chunk's W into the other buffer
            int s2 = s, kb2 = kb + 64;
            bool hasNext = true;
            if (c + 1 >= nch) { if (s < 5) { s2 = s + 1; kb2 = 0; } else hasNext = false; }
            if (hasNext) {
                const __nv_bfloat16* WH = g_wph + P.wbase[s2];
                const __nv_bfloat16* WL = g_wpl + P.wbase[s2];
                const int Kp2 = P.kp[s2];
                __nv_bfloat16* DH = sm + (((fg + 1) & 1) ? OFF_CHW1 : OFF_CHW0);
                __nv_bfloat16* DL = DH + 128 * CH_STR;
                for (int idx = tid; idx < 1024; idx += 256) {
                    int n = idx >> 3, seg = idx & 7;
                    uint32_t so = n * CH_STR + seg * 8;
                    cp16(smem_u32(DH + so), WH + (size_t)n * Kp2 + kb2 + seg * 8);
                    cp16(smem_u32(DL + so), WL + (size_t)n * Kp2 + kb2 + seg * 8);
                }
                asm volatile("cp.async.commit_group;" ::: "memory");
            }

            if (!fromAct) {
                for (int idx = tid; idx < 2048; idx += 256) {
                    int r = idx >> 5, clp = idx & 31;
                    int gk = kb + (clp << 1);
                    float v0 = 0.f, v1 = 0.f;
                    if (s == 0) {
                        if (gk < 128) {
                            float2 t = *(const float2*)(memory + (size_t)ida_s[r] * 128 + gk);
                            v0 = t.x; v1 = t.y;
                        } else if (gk < 256) {
                            float2 t = *(const float2*)(memory + (size_t)idb_s[r] * 128 + (gk - 128));
                            v0 = t.x; v1 = t.y;
                        } else if (gk < 384) {
                            float2 t = *(const float2*)(edge + (size_t)(brow + r) * 128 + (gk - 256));
                            v0 = t.x; v1 = t.y;
                        } else if (gk < 484) {
                            int t0 = gk - 384;
                            v0 = cosf(ts_s[r] * tw_s[t0] + tb_s[t0]);
                            if (t0 + 1 < TIMED) v1 = cosf(ts_s[r] * tw_s[t0 + 1] + tb_s[t0 + 1]);
                        }
                    } else if (s == 4) {
                        int t0 = gk - 128;
                        if (t0 < TIMED)     v0 = cosf(ts_s[r] * tw_s[t0] + tb_s[t0]);
                        if (t0 + 1 < TIMED) v1 = cosf(ts_s[r] * tw_s[t0 + 1] + tb_s[t0 + 1]);
                    } else { // s == 5
                        int e0 = gk - 128;
                        float2 t = *(const float2*)(P.emb + (size_t)(brow + r) * 128 + e0);
                        v0 = t.x; v1 = t.y;
                    }
                    uint32_t hi, lo; split2(v0, v1, hi, lo);
                    *(uint32_t*)(CHA_H + r * CH_STR + (clp << 1)) = hi;
                    *(uint32_t*)(CHA_L + r * CH_STR + (clp << 1)) = lo;
                }
            }

            if (hasNext) asm volatile("cp.async.wait_group 1;" ::: "memory");
            else         asm volatile("cp.async.wait_group 0;" ::: "memory");
            __syncthreads();

            const __nv_bfloat16* AbH = fromAct ? ACT_H : CHA_H;
            const __nv_bfloat16* AbL = fromAct ? ACT_L : CHA_L;
            const int astr = fromAct ? ACT_STR : CH_STR;
            const int acol = fromAct ? kb : 0;
            const __nv_bfloat16* WHs = sm + ((fg & 1) ? OFF_CHW1 : OFF_CHW0);
            const __nv_bfloat16* WLs = WHs + 128 * CH_STR;

            #pragma unroll
            for (int kk = 0; kk < 64; kk += 16) {
                uint32_t ah[4], al[4];
                ldm_x4(ah, smem_u32(AbH + (wm + arow) * astr + acol + kk + akoff));
                ldm_x4(al, smem_u32(AbL + (wm + arow) * astr + acol + kk + akoff));
                #pragma unroll
                for (int nb = 0; nb < 4; nb++) {
                    uint32_t rh[4], rlw[4];
                    ldm_x4(rh,  smem_u32(WHs + (wn + nb * 16 + brw2) * CH_STR + kk + bkoff));
                    ldm_x4(rlw, smem_u32(WLs + (wn + nb * 16 + brw2) * CH_STR + kk + bkoff));
                    mma_bf16(acc[nb * 2],     ah, rh);
                    mma_bf16(acc[nb * 2],     ah, rlw);
                    mma_bf16(acc[nb * 2],     al, rh);
                    mma_bf16(acc[nb * 2 + 1], ah, rh + 2);
                    mma_bf16(acc[nb * 2 + 1], ah, rlw + 2);
                    mma_bf16(acc[nb * 2 + 1], al, rh + 2);
                }
            }
            __syncthreads();
        }

        const float* bias = P.bias[s];
        #pragma unroll
        for (int ni = 0; ni < 8; ni++) {
            int col = wn + ni * 8 + q * 2;
            float bv0 = bias[col], bv1 = bias[col + 1];
            #pragma unroll
            for (int h = 0; h < 2; h++) {
                int row = wm + g + h * 8;
                float v0 = acc[ni][h * 2] + bv0;
                float v1 = acc[ni][h * 2 + 1] + bv1;
                if (rl[s]) { v0 = fmaxf(v0, 0.f); v1 = fmaxf(v1, 0.f); }
                if (s < 5) {
                    uint32_t hi, lo; split2(v0, v1, hi, lo);
                    *(uint32_t*)(ACT_H + row * ACT_STR + col) = hi;
                    *(uint32_t*)(ACT_L + row * ACT_STR + col) = lo;
                    if (s == 4)
                        *(float2*)(P.ut + (size_t)(brow + row) * 128 + col) = make_float2(v0, v1);
                } else {
                    *(float2*)(P.outp + (size_t)(brow + row) * 128 + col) = make_float2(v0, v1);
                }
            }
        }
        __syncthreads();
    }
}

// ---------------- winner + memory output ----------------
__global__ void win_init_kernel(int nodes)
{
    int i = blockIdx.x * blockDim.x + threadIdx.x;
    if (i < nodes) g_win[i] = -1;
}
__global__ void win_mark_kernel(const int* __restrict__ src, const int* __restrict__ dst, int Bn)
{
    int i = blockIdx.x * blockDim.x + threadIdx.x;
    if (i < 2 * Bn) {
        int id = (i < Bn) ? src[i] : dst[i - Bn];
        atomicMax(&g_win[id], i);
    }
}
// UNCONDITIONAL bulk copy: pure memcpy with streaming hints + 4x MLP unroll.
// Winner rows get overwritten later by scatter_win (which runs after copy+chain).
// 256 threads x <=32 regs = 8192 regs/CTA -> exactly fits the chain's freed regs.
#define COPY_BLOCKS 2048
__global__ void __maxnreg__(32)
copy_pass_kernel(const float4* __restrict__ mem4, float4* __restrict__ out4, size_t n4)
{
    size_t base = (size_t)blockIdx.x * (blockDim.x * 4) + threadIdx.x;
    size_t step = (size_t)gridDim.x * (blockDim.x * 4);
    for (size_t i = base; i < n4; i += step) {
        size_t i1 = i + 256, i2 = i + 512, i3 = i + 768;
        float4 a0 = __ldcs(mem4 + i);
        float4 a1, a2, a3;
        bool b1 = i1 < n4, b2 = i2 < n4, b3 = i3 < n4;
        if (b1) a1 = __ldcs(mem4 + i1);
        if (b2) a2 = __ldcs(mem4 + i2);
        if (b3) a3 = __ldcs(mem4 + i3);
        __stcs(out4 + i, a0);
        if (b1) __stcs(out4 + i1, a1);
        if (b2) __stcs(out4 + i2, a2);
        if (b3) __stcs(out4 + i3, a3);
    }
}
__global__ void scatter_win_kernel(const int* __restrict__ src, const int* __restrict__ dst,
                                   const float* __restrict__ ut, const float* __restrict__ it,
                                   float* __restrict__ out_mem, int Bn)
{
    int i = blockIdx.x;
    int j = threadIdx.x;
    int id;
    const float* row;
    if (i < Bn) { id = src[i];      row = ut + (size_t)i * 128; }
    else        { id = dst[i - Bn]; row = it + (size_t)(i - Bn) * 128; }
    if (g_win[id] == i)
        out_mem[(size_t)id * 128 + j] = row[j];
}

// ---------------- launch ----------------
extern "C" void kernel_launch(void* const* d_in, const int* in_sizes, int n_in,
                              void* d_out, int out_size)
{
    const float* src_emb = (const float*)d_in[0];
    const float* dst_emb = (const float*)d_in[1];
    const int*   src_ids = (const int*)  d_in[2];
    const int*   dst_ids = (const int*)  d_in[3];
    const float* edge    = (const float*)d_in[4];
    const float* ts      = (const float*)d_in[5];
    const float* memory  = (const float*)d_in[6];
    const float* tw      = (const float*)d_in[7];
    const float* tb      = (const float*)d_in[8];
    const float* Wu1 = (const float*)d_in[9];   const float* bu1 = (const float*)d_in[10];
    const float* Wu2 = (const float*)d_in[11];  const float* bu2 = (const float*)d_in[12];
    const float* Wi1 = (const float*)d_in[13];  const float* bi1 = (const float*)d_in[14];
    const float* Wi2 = (const float*)d_in[15];  const float* bi2 = (const float*)d_in[16];
    const float* Wp1 = (const float*)d_in[17];  const float* bp1 = (const float*)d_in[18];
    const float* Wp2 = (const float*)d_in[19];  const float* bp2 = (const float*)d_in[20];
    const float* Wt1 = (const float*)d_in[21];  const float* bt1 = (const float*)d_in[22];
    const float* Wo  = (const float*)d_in[23];  const float* bo  = (const float*)d_in[24];

    const int Bn    = in_sizes[5];
    const int nodes = in_sizes[6] / MEMD;
    float* out = (float*)d_out;

    float *ut, *it;
    cudaGetSymbolAddress((void**)&ut, g_ut);
    cudaGetSymbolAddress((void**)&it, g_it);

    const int SMEM_DYN = SMEM_ELE * (int)sizeof(__nv_bfloat16);
    cudaFuncSetAttribute(chain_kernel, cudaFuncAttributeMaxDynamicSharedMemorySize, SMEM_DYN);

    static cudaStream_t s2 = nullptr;
    static cudaEvent_t evFork = nullptr, evCopy = nullptr;
    if (!s2) {
        cudaStreamCreateWithFlags(&s2, cudaStreamNonBlocking);
        cudaEventCreateWithFlags(&evFork, cudaEventDisableTiming);
        cudaEventCreateWithFlags(&evCopy, cudaEventDisableTiming);
    }

    long outHead = (long)2 * Bn * MEMD;
    bool hasMem = ((long)out_size >= outHead + (long)nodes * MEMD);
    float* out_mem = out + outHead;

    // fork: pure bulk copy starts immediately on s2 (no dependencies at all)
    cudaEventRecord(evFork, 0);
    cudaStreamWaitEvent(s2, evFork, 0);
    if (hasMem) {
        copy_pass_kernel<<<COPY_BLOCKS, 256, 0, s2>>>(
            (const float4*)memory, (float4*)out_mem, (size_t)nodes * 32);
    }
    cudaEventRecord(evCopy, s2);

    // main stream: winner calc (fast) -> weight prep -> chain
    win_init_kernel<<<(nodes + 255) / 256, 256>>>(nodes);
    win_mark_kernel<<<(2 * Bn + 255) / 256, 256>>>(src_ids, dst_ids, Bn);

    PrepArgs pa;
    const float* Ws[8] = {Wu1, Wi1, Wu2, Wi2, Wp1, Wp2, Wt1, Wo};
    int Ks[8]  = {484, 484, 128, 128, 128, 128, 228, 256};
    int Kps[8] = {512, 512, 128, 128, 128, 128, 256, 256};
    int Bs[8]  = {PB_U1, PB_I1, PB_U2, PB_I2, PB_P1, PB_P2, PB_T1, PB_O};
    int cum = 0;
    for (int i = 0; i < 8; i++) {
        pa.W[i] = Ws[i]; pa.K[i] = Ks[i]; pa.Kp[i] = Kps[i]; pa.base[i] = Bs[i];
        pa.cum[i] = cum; cum += Kps[i];
    }
    pa.cum[8] = cum;
    prep_all_kernel<<<cum, 128>>>(pa);

    ChainArgs U, I;
    U.ida = src_ids; U.idb = dst_ids; U.emb = src_emb;
    int ubase[6] = {PB_U1, PB_U2, PB_P1, PB_P2, PB_T1, PB_O};
    int ibase[6] = {PB_I1, PB_I2, PB_P1, PB_P2, PB_T1, PB_O};
    int kps6[6]  = {512, 128, 128, 128, 256, 256};
    for (int s = 0; s < 6; s++) { U.wbase[s] = ubase[s]; I.wbase[s] = ibase[s]; U.kp[s] = I.kp[s] = kps6[s]; }
    U.bias[0] = bu1; U.bias[1] = bu2; U.bias[2] = bp1; U.bias[3] = bp2; U.bias[4] = bt1; U.bias[5] = bo;
    I.bias[0] = bi1; I.bias[1] = bi2; I.bias[2] = bp1; I.bias[3] = bp2; I.bias[4] = bt1; I.bias[5] = bo;
    U.ut = ut; U.outp = out;
    I.ida = dst_ids; I.idb = src_ids; I.emb = dst_emb;
    I.ut = it; I.outp = out + (size_t)Bn * MEMD;

    dim3 grid(Bn / MROWS, 2);
    chain_kernel<<<grid, 256, SMEM_DYN>>>(U, I, memory, edge, ts, tw, tb);

    // join: scatter overwrites winner rows after copy AND chain AND win_mark
    if (hasMem) {
        cudaStreamWaitEvent(0, evCopy, 0);
        scatter_win_kernel<<<2 * Bn, 128>>>(src_ids, dst_ids, ut, it, out_mem, Bn);
    }
}

// round 16
// speedup vs baseline: 1.1307x; 1.1307x over previous
#include <cuda_runtime.h>
#include <cuda_bf16.h>
#include <math.h>
#include <stdint.h>

// ---------------- problem constants ----------------
#define BB       16384
#define MEMD     128
#define TIMED    100
#define MAXNODES 1100000

// ---------------- device scratch ----------------
__device__ float g_ut[BB * MEMD];
__device__ float g_it[BB * MEMD];
__device__ int   g_win[MAXNODES];
// pre-split bf16 weight pools, [128, Kp] K-major per weight, concatenated
#define POOL_ELE (2048 * 128)
__device__ __align__(16) __nv_bfloat16 g_wph[POOL_ELE];
__device__ __align__(16) __nv_bfloat16 g_wpl[POOL_ELE];
#define PB_U1 0
#define PB_I1 65536
#define PB_U2 131072
#define PB_I2 147456
#define PB_P1 163840
#define PB_P2 180224
#define PB_T1 196608
#define PB_O  229376

// ---------------- helpers ----------------
__device__ __forceinline__ uint32_t smem_u32(const void* p) {
    uint32_t a;
    asm("{ .reg .u64 t; cvta.to.shared.u64 t, %1; cvt.u32.u64 %0, t; }" : "=r"(a) : "l"(p));
    return a;
}
__device__ __forceinline__ void ldm_x4(uint32_t* r, uint32_t addr) {
    asm volatile("ldmatrix.sync.aligned.m8n8.x4.shared.b16 {%0,%1,%2,%3}, [%4];"
        : "=r"(r[0]), "=r"(r[1]), "=r"(r[2]), "=r"(r[3]) : "r"(addr));
}
__device__ __forceinline__ void mma_bf16(float* c, const uint32_t* a, const uint32_t* b) {
    asm volatile("mma.sync.aligned.m16n8k16.row.col.f32.bf16.bf16.f32 "
        "{%0,%1,%2,%3}, {%4,%5,%6,%7}, {%8,%9}, {%0,%1,%2,%3};"
        : "+f"(c[0]), "+f"(c[1]), "+f"(c[2]), "+f"(c[3])
        : "r"(a[0]), "r"(a[1]), "r"(a[2]), "r"(a[3]), "r"(b[0]), "r"(b[1]));
}
__device__ __forceinline__ void cp16(uint32_t smaddr, const void* g) {
    asm volatile("cp.async.ca.shared.global [%0], [%1], 16;" :: "r"(smaddr), "l"(g));
}
__device__ __forceinline__ void split2(float v0, float v1, uint32_t& hi, uint32_t& lo) {
    __nv_bfloat16 h0 = __float2bfloat16(v0);
    __nv_bfloat16 h1 = __float2bfloat16(v1);
    __nv_bfloat16 l0 = __float2bfloat16(v0 - __bfloat162float(h0));
    __nv_bfloat16 l1 = __float2bfloat16(v1 - __bfloat162float(h1));
    __nv_bfloat162 H = __halves2bfloat162(h0, h1);
    __nv_bfloat162 L = __halves2bfloat162(l0, l1);
    hi = *(uint32_t*)&H; lo = *(uint32_t*)&L;
}

// ---------------- fused weight prep ----------------
struct PrepArgs {
    const float* W[8];
    int K[8];
    int Kp[8];
    int base[8];
    int cum[9];
};
__global__ void prep_all_kernel(PrepArgs pa)
{
    int kglob = blockIdx.x;
    int n = threadIdx.x;
    int w = 0;
    #pragma unroll
    for (int i = 0; i < 8; i++) if (kglob >= pa.cum[i + 1]) w = i + 1;
    int k = kglob - pa.cum[w];
    float v = (k < pa.K[w]) ? pa.W[w][(size_t)k * 128 + n] : 0.f;
    __nv_bfloat16 hi = __float2bfloat16(v);
    __nv_bfloat16 lo = __float2bfloat16(v - __bfloat162float(hi));
    int Kp = pa.Kp[w];
    g_wph[pa.base[w] + (size_t)n * Kp + k] = hi;
    g_wpl[pa.base[w] + (size_t)n * Kp + k] = lo;
}

// ---------------- fused chain kernel (3 CTA/SM) ----------------
struct ChainArgs {
    const int* ida;
    const int* idb;
    const float* emb;
    int wbase[6];
    int kp[6];
    const float* bias[6];
    float* ut;
    float* outp;
};

#define MROWS 64
#define ACT_STR 136
#define CH_STR  72
// bf16-element offsets. CHA aliases the head of ACT (dead when CHA is live).
// SINGLE CHW buffer: dynamic smem = 2*64*136 + 2*128*72 = 35840 ele = 70KB
// -> 3 CTAs/SM (216KB dyn + static < 228KB), 24 warps/SM.
#define OFF_ACT_H 0
#define OFF_ACT_L (MROWS*ACT_STR)
#define OFF_CHA_H 0
#define OFF_CHA_L (MROWS*CH_STR)
#define OFF_CHW   (2*MROWS*ACT_STR)
#define SMEM_ELE  (OFF_CHW + 2*128*CH_STR)   // 35840 ele = 70KB

// __maxnreg__(80): 768 thr x 80 = 61440 <= 64K regs -> 3 CTAs fit.
__global__ void __maxnreg__(80)
chain_kernel(ChainArgs au, ChainArgs ai,
             const float* __restrict__ memory,
             const float* __restrict__ edge,
             const float* __restrict__ ts,
             const float* __restrict__ tw,
             const float* __restrict__ tb)
{
    extern __shared__ __nv_bfloat16 sm[];
    __nv_bfloat16* ACT_H = sm + OFF_ACT_H;
    __nv_bfloat16* ACT_L = sm + OFF_ACT_L;
    __nv_bfloat16* CHA_H = sm + OFF_CHA_H;
    __nv_bfloat16* CHA_L = sm + OFF_CHA_L;
    __nv_bfloat16* CHW_H = sm + OFF_CHW;
    __nv_bfloat16* CHW_L = sm + OFF_CHW + 128 * CH_STR;

    __shared__ int   ida_s[MROWS], idb_s[MROWS];
    __shared__ float ts_s[MROWS], tw_s[TIMED], tb_s[TIMED];

    const ChainArgs P = blockIdx.y ? ai : au;
    const int tid  = threadIdx.x;
    const int lane = tid & 31;
    const int wid  = tid >> 5;
    const int wm   = (wid & 3) * 16;
    const int wn   = (wid >> 2) * 64;
    const int brow = blockIdx.x * MROWS;

    if (tid < MROWS) {
        ida_s[tid] = P.ida[brow + tid];
        idb_s[tid] = P.idb[brow + tid];
        ts_s[tid]  = ts[brow + tid];
    }
    if (tid >= 128 && tid < 128 + TIMED) {
        tw_s[tid - 128] = tw[tid - 128];
        tb_s[tid - 128] = tb[tid - 128];
    }
    __syncthreads();

    const int arow  = (lane & 7) + ((lane >> 3) & 1) * 8;
    const int akoff = (lane >> 4) * 8;
    const int brw2  = ((lane >> 4) << 3) + (lane & 7);
    const int bkoff = ((lane >> 3) & 1) * 8;
    const int g = lane >> 2, q = lane & 3;

    const int rl[6] = {1, 0, 1, 0, 1, 0};

    for (int s = 0; s < 6; s++) {
        const int Kp = P.kp[s];
        const __nv_bfloat16* WH = g_wph + P.wbase[s];
        const __nv_bfloat16* WL = g_wpl + P.wbase[s];
        float acc[8][4];
        #pragma unroll
        for (int j = 0; j < 8; j++)
            #pragma unroll
            for (int k = 0; k < 4; k++) acc[j][k] = 0.f;

        const int nch = Kp >> 6;
        for (int c = 0; c < nch; c++) {
            const int kb = c << 6;
            const bool fromAct = (s > 0) && (kb < 128);

            // W chunk via cp.async (single buffer; 3rd CTA hides the wait)
            for (int idx = tid; idx < 1024; idx += 256) {
                int n = idx >> 3, seg = idx & 7;
                uint32_t so = n * CH_STR + seg * 8;
                cp16(smem_u32(CHW_H + so), WH + (size_t)n * Kp + kb + seg * 8);
                cp16(smem_u32(CHW_L + so), WL + (size_t)n * Kp + kb + seg * 8);
            }
            asm volatile("cp.async.commit_group;" ::: "memory");

            if (!fromAct) {
                for (int idx = tid; idx < 2048; idx += 256) {
                    int r = idx >> 5, clp = idx & 31;
                    int gk = kb + (clp << 1);
                    float v0 = 0.f, v1 = 0.f;
                    if (s == 0) {
                        if (gk < 128) {
                            float2 t = *(const float2*)(memory + (size_t)ida_s[r] * 128 + gk);
                            v0 = t.x; v1 = t.y;
                        } else if (gk < 256) {
                            float2 t = *(const float2*)(memory + (size_t)idb_s[r] * 128 + (gk - 128));
                            v0 = t.x; v1 = t.y;
                        } else if (gk < 384) {
                            float2 t = *(const float2*)(edge + (size_t)(brow + r) * 128 + (gk - 256));
                            v0 = t.x; v1 = t.y;
                        } else if (gk < 484) {
                            int t0 = gk - 384;
                            v0 = cosf(ts_s[r] * tw_s[t0] + tb_s[t0]);
                            if (t0 + 1 < TIMED) v1 = cosf(ts_s[r] * tw_s[t0 + 1] + tb_s[t0 + 1]);
                        }
                    } else if (s == 4) {
                        int t0 = gk - 128;
                        if (t0 < TIMED)     v0 = cosf(ts_s[r] * tw_s[t0] + tb_s[t0]);
                        if (t0 + 1 < TIMED) v1 = cosf(ts_s[r] * tw_s[t0 + 1] + tb_s[t0 + 1]);
                    } else { // s == 5
                        int e0 = gk - 128;
                        float2 t = *(const float2*)(P.emb + (size_t)(brow + r) * 128 + e0);
                        v0 = t.x; v1 = t.y;
                    }
                    uint32_t hi, lo; split2(v0, v1, hi, lo);
                    *(uint32_t*)(CHA_H + r * CH_STR + (clp << 1)) = hi;
                    *(uint32_t*)(CHA_L + r * CH_STR + (clp << 1)) = lo;
                }
            }

            asm volatile("cp.async.wait_group 0;" ::: "memory");
            __syncthreads();

            const __nv_bfloat16* AbH = fromAct ? ACT_H : CHA_H;
            const __nv_bfloat16* AbL = fromAct ? ACT_L : CHA_L;
            const int astr = fromAct ? ACT_STR : CH_STR;
            const int acol = fromAct ? kb : 0;

            #pragma unroll
            for (int kk = 0; kk < 64; kk += 16) {
                uint32_t ah[4], al[4];
                ldm_x4(ah, smem_u32(AbH + (wm + arow) * astr + acol + kk + akoff));
                ldm_x4(al, smem_u32(AbL + (wm + arow) * astr + acol + kk + akoff));
                #pragma unroll
                for (int nb = 0; nb < 4; nb++) {
                    uint32_t rh[4], rlw[4];
                    ldm_x4(rh,  smem_u32(CHW_H + (wn + nb * 16 + brw2) * CH_STR + kk + bkoff));
                    ldm_x4(rlw, smem_u32(CHW_L + (wn + nb * 16 + brw2) * CH_STR + kk + bkoff));
                    mma_bf16(acc[nb * 2],     ah, rh);
                    mma_bf16(acc[nb * 2],     ah, rlw);
                    mma_bf16(acc[nb * 2],     al, rh);
                    mma_bf16(acc[nb * 2 + 1], ah, rh + 2);
                    mma_bf16(acc[nb * 2 + 1], ah, rlw + 2);
                    mma_bf16(acc[nb * 2 + 1], al, rh + 2);
                }
            }
            __syncthreads();
        }

        const float* bias = P.bias[s];
        #pragma unroll
        for (int ni = 0; ni < 8; ni++) {
            int col = wn + ni * 8 + q * 2;
            float bv0 = bias[col], bv1 = bias[col + 1];
            #pragma unroll
            for (int h = 0; h < 2; h++) {
                int row = wm + g + h * 8;
                float v0 = acc[ni][h * 2] + bv0;
                float v1 = acc[ni][h * 2 + 1] + bv1;
                if (rl[s]) { v0 = fmaxf(v0, 0.f); v1 = fmaxf(v1, 0.f); }
                if (s < 5) {
                    uint32_t hi, lo; split2(v0, v1, hi, lo);
                    *(uint32_t*)(ACT_H + row * ACT_STR + col) = hi;
                    *(uint32_t*)(ACT_L + row * ACT_STR + col) = lo;
                    if (s == 4)
                        *(float2*)(P.ut + (size_t)(brow + row) * 128 + col) = make_float2(v0, v1);
                } else {
                    *(float2*)(P.outp + (size_t)(brow + row) * 128 + col) = make_float2(v0, v1);
                }
            }
        }
        __syncthreads();
    }
}

// ---------------- winner + memory output ----------------
__global__ void win_init_kernel(int nodes)
{
    int i = blockIdx.x * blockDim.x + threadIdx.x;
    if (i < nodes) g_win[i] = -1;
}
__global__ void win_mark_kernel(const int* __restrict__ src, const int* __restrict__ dst, int Bn)
{
    int i = blockIdx.x * blockDim.x + threadIdx.x;
    if (i < 2 * Bn) {
        int id = (i < Bn) ? src[i] : dst[i - Bn];
        atomicMax(&g_win[id], i);
    }
}
#define COPY_BLOCKS 4096
__global__ void __maxnreg__(32)
copy_pass_kernel(const float4* __restrict__ mem4, float4* __restrict__ out4, int nodes)
{
    size_t total = (size_t)nodes * 32;
    size_t stride = (size_t)COPY_BLOCKS * 128;
    for (size_t idx = (size_t)blockIdx.x * 128 + threadIdx.x; idx < total; idx += stride) {
        int row = (int)(idx >> 5);
        if (g_win[row] < 0)
            out4[idx] = mem4[idx];
    }
}
__global__ void scatter_win_kernel(const int* __restrict__ src, const int* __restrict__ dst,
                                   const float* __restrict__ ut, const float* __restrict__ it,
                                   float* __restrict__ out_mem, int Bn)
{
    int i = blockIdx.x;
    int j = threadIdx.x;
    int id;
    const float* row;
    if (i < Bn) { id = src[i];      row = ut + (size_t)i * 128; }
    else        { id = dst[i - Bn]; row = it + (size_t)(i - Bn) * 128; }
    if (g_win[id] == i)
        out_mem[(size_t)id * 128 + j] = row[j];
}

// ---------------- launch ----------------
extern "C" void kernel_launch(void* const* d_in, const int* in_sizes, int n_in,
                              void* d_out, int out_size)
{
    const float* src_emb = (const float*)d_in[0];
    const float* dst_emb = (const float*)d_in[1];
    const int*   src_ids = (const int*)  d_in[2];
    const int*   dst_ids = (const int*)  d_in[3];
    const float* edge    = (const float*)d_in[4];
    const float* ts      = (const float*)d_in[5];
    const float* memory  = (const float*)d_in[6];
    const float* tw      = (const float*)d_in[7];
    const float* tb      = (const float*)d_in[8];
    const float* Wu1 = (const float*)d_in[9];   const float* bu1 = (const float*)d_in[10];
    const float* Wu2 = (const float*)d_in[11];  const float* bu2 = (const float*)d_in[12];
    const float* Wi1 = (const float*)d_in[13];  const float* bi1 = (const float*)d_in[14];
    const float* Wi2 = (const float*)d_in[15];  const float* bi2 = (const float*)d_in[16];
    const float* Wp1 = (const float*)d_in[17];  const float* bp1 = (const float*)d_in[18];
    const float* Wp2 = (const float*)d_in[19];  const float* bp2 = (const float*)d_in[20];
    const float* Wt1 = (const float*)d_in[21];  const float* bt1 = (const float*)d_in[22];
    const float* Wo  = (const float*)d_in[23];  const float* bo  = (const float*)d_in[24];

    const int Bn    = in_sizes[5];
    const int nodes = in_sizes[6] / MEMD;
    float* out = (float*)d_out;

    float *ut, *it;
    cudaGetSymbolAddress((void**)&ut, g_ut);
    cudaGetSymbolAddress((void**)&it, g_it);

    const int SMEM_DYN = SMEM_ELE * (int)sizeof(__nv_bfloat16);   // 70KB
    cudaFuncSetAttribute(chain_kernel, cudaFuncAttributeMaxDynamicSharedMemorySize, SMEM_DYN);

    static cudaStream_t s2 = nullptr;
    static cudaEvent_t evFork = nullptr, evMark = nullptr, evCopy = nullptr;
    if (!s2) {
        cudaStreamCreateWithFlags(&s2, cudaStreamNonBlocking);
        cudaEventCreateWithFlags(&evFork, cudaEventDisableTiming);
        cudaEventCreateWithFlags(&evMark, cudaEventDisableTiming);
        cudaEventCreateWithFlags(&evCopy, cudaEventDisableTiming);
    }

    long outHead = (long)2 * Bn * MEMD;
    bool hasMem = ((long)out_size >= outHead + (long)nodes * MEMD);
    float* out_mem = out + outHead;

    cudaEventRecord(evFork, 0);
    cudaStreamWaitEvent(s2, evFork, 0);

    // (1) weight prep on main stream
    PrepArgs pa;
    const float* Ws[8] = {Wu1, Wi1, Wu2, Wi2, Wp1, Wp2, Wt1, Wo};
    int Ks[8]  = {484, 484, 128, 128, 128, 128, 228, 256};
    int Kps[8] = {512, 512, 128, 128, 128, 128, 256, 256};
    int Bs[8]  = {PB_U1, PB_I1, PB_U2, PB_I2, PB_P1, PB_P2, PB_T1, PB_O};
    int cum = 0;
    for (int i = 0; i < 8; i++) {
        pa.W[i] = Ws[i]; pa.K[i] = Ks[i]; pa.Kp[i] = Kps[i]; pa.base[i] = Bs[i];
        pa.cum[i] = cum; cum += Kps[i];
    }
    pa.cum[8] = cum;
    prep_all_kernel<<<cum, 128>>>(pa);

    // (2,3) winner calc on side stream
    win_init_kernel<<<(nodes + 255) / 256, 256, 0, s2>>>(nodes);
    win_mark_kernel<<<(2 * Bn + 255) / 256, 256, 0, s2>>>(src_ids, dst_ids, Bn);
    cudaEventRecord(evMark, s2);

    // (4) fused chain
    ChainArgs U, I;
    U.ida = src_ids; U.idb = dst_ids; U.emb = src_emb;
    int ubase[6] = {PB_U1, PB_U2, PB_P1, PB_P2, PB_T1, PB_O};
    int ibase[6] = {PB_I1, PB_I2, PB_P1, PB_P2, PB_T1, PB_O};
    int kps6[6]  = {512, 128, 128, 128, 256, 256};
    for (int s = 0; s < 6; s++) { U.wbase[s] = ubase[s]; I.wbase[s] = ibase[s]; U.kp[s] = I.kp[s] = kps6[s]; }
    U.bias[0] = bu1; U.bias[1] = bu2; U.bias[2] = bp1; U.bias[3] = bp2; U.bias[4] = bt1; U.bias[5] = bo;
    I.bias[0] = bi1; I.bias[1] = bi2; I.bias[2] = bp1; I.bias[3] = bp2; I.bias[4] = bt1; I.bias[5] = bo;
    U.ut = ut; U.outp = out;
    I.ida = dst_ids; I.idb = src_ids; I.emb = dst_emb;
    I.ut = it; I.outp = out + (size_t)Bn * MEMD;

    dim3 grid(Bn / MROWS, 2);
    chain_kernel<<<grid, 256, SMEM_DYN>>>(U, I, memory, edge, ts, tw, tb);

    // (5) bulk copy on side stream (after win_mark)
    if (hasMem) {
        copy_pass_kernel<<<COPY_BLOCKS, 128, 0, s2>>>(
            (const float4*)memory, (float4*)out_mem, nodes);
    }
    cudaEventRecord(evCopy, s2);

    // (6) winner scatter after chain + winner calc
    if (hasMem) {
        cudaStreamWaitEvent(0, evMark, 0);
        scatter_win_kernel<<<2 * Bn, 128>>>(src_ids, dst_ids, ut, it, out_mem, Bn);
    }
    cudaStreamWaitEvent(0, evCopy, 0);
}

// round 17
// speedup vs baseline: 1.3020x; 1.1515x over previous
#include <cuda_runtime.h>
#include <cuda_bf16.h>
#include <math.h>
#include <stdint.h>

// ---------------- problem constants ----------------
#define BB       16384
#define MEMD     128
#define TIMED    100
#define MAXNODES 1100000

// ---------------- device scratch ----------------
__device__ float g_ut[BB * MEMD];
__device__ float g_it[BB * MEMD];
__device__ int   g_win[MAXNODES];
// pre-split bf16 weight pools, [128, Kp] K-major per weight, concatenated
#define POOL_ELE (2048 * 128)
__device__ __align__(16) __nv_bfloat16 g_wph[POOL_ELE];
__device__ __align__(16) __nv_bfloat16 g_wpl[POOL_ELE];
#define PB_U1 0
#define PB_I1 65536
#define PB_U2 131072
#define PB_I2 147456
#define PB_P1 163840
#define PB_P2 180224
#define PB_T1 196608
#define PB_O  229376

// ---------------- helpers ----------------
__device__ __forceinline__ uint32_t smem_u32(const void* p) {
    uint32_t a;
    asm("{ .reg .u64 t; cvta.to.shared.u64 t, %1; cvt.u32.u64 %0, t; }" : "=r"(a) : "l"(p));
    return a;
}
__device__ __forceinline__ void ldm_x4(uint32_t* r, uint32_t addr) {
    asm volatile("ldmatrix.sync.aligned.m8n8.x4.shared.b16 {%0,%1,%2,%3}, [%4];"
        : "=r"(r[0]), "=r"(r[1]), "=r"(r[2]), "=r"(r[3]) : "r"(addr));
}
__device__ __forceinline__ void mma_bf16(float* c, const uint32_t* a, const uint32_t* b) {
    asm volatile("mma.sync.aligned.m16n8k16.row.col.f32.bf16.bf16.f32 "
        "{%0,%1,%2,%3}, {%4,%5,%6,%7}, {%8,%9}, {%0,%1,%2,%3};"
        : "+f"(c[0]), "+f"(c[1]), "+f"(c[2]), "+f"(c[3])
        : "r"(a[0]), "r"(a[1]), "r"(a[2]), "r"(a[3]), "r"(b[0]), "r"(b[1]));
}
__device__ __forceinline__ void cp16(uint32_t smaddr, const void* g) {
    asm volatile("cp.async.ca.shared.global [%0], [%1], 16;" :: "r"(smaddr), "l"(g));
}
__device__ __forceinline__ void split2(float v0, float v1, uint32_t& hi, uint32_t& lo) {
    __nv_bfloat16 h0 = __float2bfloat16(v0);
    __nv_bfloat16 h1 = __float2bfloat16(v1);
    __nv_bfloat16 l0 = __float2bfloat16(v0 - __bfloat162float(h0));
    __nv_bfloat16 l1 = __float2bfloat16(v1 - __bfloat162float(h1));
    __nv_bfloat162 H = __halves2bfloat162(h0, h1);
    __nv_bfloat162 L = __halves2bfloat162(l0, l1);
    hi = *(uint32_t*)&H; lo = *(uint32_t*)&L;
}

// ---------------- fused weight prep ----------------
struct PrepArgs {
    const float* W[8];
    int K[8];
    int Kp[8];
    int base[8];
    int cum[9];
};
__global__ void prep_all_kernel(PrepArgs pa)
{
    int kglob = blockIdx.x;
    int n = threadIdx.x;
    int w = 0;
    #pragma unroll
    for (int i = 0; i < 8; i++) if (kglob >= pa.cum[i + 1]) w = i + 1;
    int k = kglob - pa.cum[w];
    float v = (k < pa.K[w]) ? pa.W[w][(size_t)k * 128 + n] : 0.f;
    __nv_bfloat16 hi = __float2bfloat16(v);
    __nv_bfloat16 lo = __float2bfloat16(v - __bfloat162float(hi));
    int Kp = pa.Kp[w];
    g_wph[pa.base[w] + (size_t)n * Kp + k] = hi;
    g_wpl[pa.base[w] + (size_t)n * Kp + k] = lo;
}

// ---------------- fused chain kernel (512 thr, 32 warps/SM) ----------------
struct ChainArgs {
    const int* ida;
    const int* idb;
    const float* emb;
    int wbase[6];
    int kp[6];
    const float* bias[6];
    float* ut;
    float* outp;
};

#define CT 512                 // threads per CTA (16 warps: 4 in M x 4 in N)
#define MROWS 64
#define ACT_STR 136
#define CH_STR  72
#define OFF_ACT_H 0
#define OFF_ACT_L (MROWS*ACT_STR)
#define OFF_CHA_H 0
#define OFF_CHA_L (MROWS*CH_STR)
#define OFF_CHW   (2*MROWS*ACT_STR)
#define SMEM_ELE  (OFF_CHW + 2*128*CH_STR)   // 35840 ele = 70KB -> 2 CTA/SM (thread-capped)

// __maxnreg__(64): 1024 thr x 64 = 65536 regs -> 2 CTAs/SM exactly.
__global__ void __maxnreg__(64)
chain_kernel(ChainArgs au, ChainArgs ai,
             const float* __restrict__ memory,
             const float* __restrict__ edge,
             const float* __restrict__ ts,
             const float* __restrict__ tw,
             const float* __restrict__ tb)
{
    extern __shared__ __nv_bfloat16 sm[];
    __nv_bfloat16* ACT_H = sm + OFF_ACT_H;
    __nv_bfloat16* ACT_L = sm + OFF_ACT_L;
    __nv_bfloat16* CHA_H = sm + OFF_CHA_H;
    __nv_bfloat16* CHA_L = sm + OFF_CHA_L;
    __nv_bfloat16* CHW_H = sm + OFF_CHW;
    __nv_bfloat16* CHW_L = sm + OFF_CHW + 128 * CH_STR;

    __shared__ int   ida_s[MROWS], idb_s[MROWS];
    __shared__ float ts_s[MROWS], tw_s[TIMED], tb_s[TIMED];

    const ChainArgs P = blockIdx.y ? ai : au;
    const int tid  = threadIdx.x;
    const int lane = tid & 31;
    const int wid  = tid >> 5;          // 0..15
    const int wm   = (wid & 3) * 16;    // 4 warps in M
    const int wn   = (wid >> 2) * 32;   // 4 warps in N, 32 cols each
    const int brow = blockIdx.x * MROWS;

    if (tid < MROWS) {
        ida_s[tid] = P.ida[brow + tid];
        idb_s[tid] = P.idb[brow + tid];
        ts_s[tid]  = ts[brow + tid];
    }
    if (tid >= 128 && tid < 128 + TIMED) {
        tw_s[tid - 128] = tw[tid - 128];
        tb_s[tid - 128] = tb[tid - 128];
    }
    __syncthreads();

    const int arow  = (lane & 7) + ((lane >> 3) & 1) * 8;
    const int akoff = (lane >> 4) * 8;
    const int brw2  = ((lane >> 4) << 3) + (lane & 7);
    const int bkoff = ((lane >> 3) & 1) * 8;
    const int g = lane >> 2, q = lane & 3;

    const int rl[6] = {1, 0, 1, 0, 1, 0};

    for (int s = 0; s < 6; s++) {
        const int Kp = P.kp[s];
        const __nv_bfloat16* WH = g_wph + P.wbase[s];
        const __nv_bfloat16* WL = g_wpl + P.wbase[s];
        float acc[4][4];
        #pragma unroll
        for (int j = 0; j < 4; j++)
            #pragma unroll
            for (int k = 0; k < 4; k++) acc[j][k] = 0.f;

        const int nch = Kp >> 6;
        for (int c = 0; c < nch; c++) {
            const int kb = c << 6;
            const bool fromAct = (s > 0) && (kb < 128);

            // W chunk via cp.async (2048 x 16B over 512 threads)
            for (int idx = tid; idx < 1024; idx += CT) {
                int n = idx >> 3, seg = idx & 7;
                uint32_t so = n * CH_STR + seg * 8;
                cp16(smem_u32(CHW_H + so), WH + (size_t)n * Kp + kb + seg * 8);
                cp16(smem_u32(CHW_L + so), WL + (size_t)n * Kp + kb + seg * 8);
            }
            asm volatile("cp.async.commit_group;" ::: "memory");

            if (!fromAct) {
                for (int idx = tid; idx < 2048; idx += CT) {
                    int r = idx >> 5, clp = idx & 31;
                    int gk = kb + (clp << 1);
                    float v0 = 0.f, v1 = 0.f;
                    if (s == 0) {
                        if (gk < 128) {
                            float2 t = *(const float2*)(memory + (size_t)ida_s[r] * 128 + gk);
                            v0 = t.x; v1 = t.y;
                        } else if (gk < 256) {
                            float2 t = *(const float2*)(memory + (size_t)idb_s[r] * 128 + (gk - 128));
                            v0 = t.x; v1 = t.y;
                        } else if (gk < 384) {
                            float2 t = *(const float2*)(edge + (size_t)(brow + r) * 128 + (gk - 256));
                            v0 = t.x; v1 = t.y;
                        } else if (gk < 484) {
                            int t0 = gk - 384;
                            v0 = cosf(ts_s[r] * tw_s[t0] + tb_s[t0]);
                            if (t0 + 1 < TIMED) v1 = cosf(ts_s[r] * tw_s[t0 + 1] + tb_s[t0 + 1]);
                        }
                    } else if (s == 4) {
                        int t0 = gk - 128;
                        if (t0 < TIMED)     v0 = cosf(ts_s[r] * tw_s[t0] + tb_s[t0]);
                        if (t0 + 1 < TIMED) v1 = cosf(ts_s[r] * tw_s[t0 + 1] + tb_s[t0 + 1]);
                    } else { // s == 5
                        int e0 = gk - 128;
                        float2 t = *(const float2*)(P.emb + (size_t)(brow + r) * 128 + e0);
                        v0 = t.x; v1 = t.y;
                    }
                    uint32_t hi, lo; split2(v0, v1, hi, lo);
                    *(uint32_t*)(CHA_H + r * CH_STR + (clp << 1)) = hi;
                    *(uint32_t*)(CHA_L + r * CH_STR + (clp << 1)) = lo;
                }
            }

            asm volatile("cp.async.wait_group 0;" ::: "memory");
            __syncthreads();

            const __nv_bfloat16* AbH = fromAct ? ACT_H : CHA_H;
            const __nv_bfloat16* AbL = fromAct ? ACT_L : CHA_L;
            const int astr = fromAct ? ACT_STR : CH_STR;
            const int acol = fromAct ? kb : 0;

            #pragma unroll
            for (int kk = 0; kk < 64; kk += 16) {
                uint32_t ah[4], al[4];
                ldm_x4(ah, smem_u32(AbH + (wm + arow) * astr + acol + kk + akoff));
                ldm_x4(al, smem_u32(AbL + (wm + arow) * astr + acol + kk + akoff));
                #pragma unroll
                for (int nb = 0; nb < 2; nb++) {
                    uint32_t rh[4], rlw[4];
                    ldm_x4(rh,  smem_u32(CHW_H + (wn + nb * 16 + brw2) * CH_STR + kk + bkoff));
                    ldm_x4(rlw, smem_u32(CHW_L + (wn + nb * 16 + brw2) * CH_STR + kk + bkoff));
                    mma_bf16(acc[nb * 2],     ah, rh);
                    mma_bf16(acc[nb * 2],     ah, rlw);
                    mma_bf16(acc[nb * 2],     al, rh);
                    mma_bf16(acc[nb * 2 + 1], ah, rh + 2);
                    mma_bf16(acc[nb * 2 + 1], ah, rlw + 2);
                    mma_bf16(acc[nb * 2 + 1], al, rh + 2);
                }
            }
            __syncthreads();
        }

        const float* bias = P.bias[s];
        #pragma unroll
        for (int ni = 0; ni < 4; ni++) {
            int col = wn + ni * 8 + q * 2;
            float bv0 = bias[col], bv1 = bias[col + 1];
            #pragma unroll
            for (int h = 0; h < 2; h++) {
                int row = wm + g + h * 8;
                float v0 = acc[ni][h * 2] + bv0;
                float v1 = acc[ni][h * 2 + 1] + bv1;
                if (rl[s]) { v0 = fmaxf(v0, 0.f); v1 = fmaxf(v1, 0.f); }
                if (s < 5) {
                    uint32_t hi, lo; split2(v0, v1, hi, lo);
                    *(uint32_t*)(ACT_H + row * ACT_STR + col) = hi;
                    *(uint32_t*)(ACT_L + row * ACT_STR + col) = lo;
                    if (s == 4)
                        *(float2*)(P.ut + (size_t)(brow + row) * 128 + col) = make_float2(v0, v1);
                } else {
                    *(float2*)(P.outp + (size_t)(brow + row) * 128 + col) = make_float2(v0, v1);
                }
            }
        }
        __syncthreads();
    }
}

// ---------------- winner + memory output ----------------
__global__ void win_init_kernel(int nodes)
{
    int i = blockIdx.x * blockDim.x + threadIdx.x;
    if (i < nodes) g_win[i] = -1;
}
__global__ void win_mark_kernel(const int* __restrict__ src, const int* __restrict__ dst, int Bn)
{
    int i = blockIdx.x * blockDim.x + threadIdx.x;
    if (i < 2 * Bn) {
        int id = (i < Bn) ? src[i] : dst[i - Bn];
        atomicMax(&g_win[id], i);
    }
}
#define COPY_BLOCKS 4096
__global__ void __maxnreg__(32)
copy_pass_kernel(const float4* __restrict__ mem4, float4* __restrict__ out4, int nodes)
{
    size_t total = (size_t)nodes * 32;
    size_t stride = (size_t)COPY_BLOCKS * 128;
    for (size_t idx = (size_t)blockIdx.x * 128 + threadIdx.x; idx < total; idx += stride) {
        int row = (int)(idx >> 5);
        if (g_win[row] < 0)
            out4[idx] = mem4[idx];
    }
}
__global__ void scatter_win_kernel(const int* __restrict__ src, const int* __restrict__ dst,
                                   const float* __restrict__ ut, const float* __restrict__ it,
                                   float* __restrict__ out_mem, int Bn)
{
    int i = blockIdx.x;
    int j = threadIdx.x;
    int id;
    const float* row;
    if (i < Bn) { id = src[i];      row = ut + (size_t)i * 128; }
    else        { id = dst[i - Bn]; row = it + (size_t)(i - Bn) * 128; }
    if (g_win[id] == i)
        out_mem[(size_t)id * 128 + j] = row[j];
}

// ---------------- launch ----------------
extern "C" void kernel_launch(void* const* d_in, const int* in_sizes, int n_in,
                              void* d_out, int out_size)
{
    const float* src_emb = (const float*)d_in[0];
    const float* dst_emb = (const float*)d_in[1];
    const int*   src_ids = (const int*)  d_in[2];
    const int*   dst_ids = (const int*)  d_in[3];
    const float* edge    = (const float*)d_in[4];
    const float* ts      = (const float*)d_in[5];
    const float* memory  = (const float*)d_in[6];
    const float* tw      = (const float*)d_in[7];
    const float* tb      = (const float*)d_in[8];
    const float* Wu1 = (const float*)d_in[9];   const float* bu1 = (const float*)d_in[10];
    const float* Wu2 = (const float*)d_in[11];  const float* bu2 = (const float*)d_in[12];
    const float* Wi1 = (const float*)d_in[13];  const float* bi1 = (const float*)d_in[14];
    const float* Wi2 = (const float*)d_in[15];  const float* bi2 = (const float*)d_in[16];
    const float* Wp1 = (const float*)d_in[17];  const float* bp1 = (const float*)d_in[18];
    const float* Wp2 = (const float*)d_in[19];  const float* bp2 = (const float*)d_in[20];
    const float* Wt1 = (const float*)d_in[21];  const float* bt1 = (const float*)d_in[22];
    const float* Wo  = (const float*)d_in[23];  const float* bo  = (const float*)d_in[24];

    const int Bn    = in_sizes[5];
    const int nodes = in_sizes[6] / MEMD;
    float* out = (float*)d_out;

    float *ut, *it;
    cudaGetSymbolAddress((void**)&ut, g_ut);
    cudaGetSymbolAddress((void**)&it, g_it);

    const int SMEM_DYN = SMEM_ELE * (int)sizeof(__nv_bfloat16);   // 70KB
    cudaFuncSetAttribute(chain_kernel, cudaFuncAttributeMaxDynamicSharedMemorySize, SMEM_DYN);

    static cudaStream_t s2 = nullptr;
    static cudaEvent_t evFork = nullptr, evMark = nullptr, evCopy = nullptr;
    if (!s2) {
        cudaStreamCreateWithFlags(&s2, cudaStreamNonBlocking);
        cudaEventCreateWithFlags(&evFork, cudaEventDisableTiming);
        cudaEventCreateWithFlags(&evMark, cudaEventDisableTiming);
        cudaEventCreateWithFlags(&evCopy, cudaEventDisableTiming);
    }

    long outHead = (long)2 * Bn * MEMD;
    bool hasMem = ((long)out_size >= outHead + (long)nodes * MEMD);
    float* out_mem = out + outHead;

    cudaEventRecord(evFork, 0);
    cudaStreamWaitEvent(s2, evFork, 0);

    // (1) weight prep on main stream
    PrepArgs pa;
    const float* Ws[8] = {Wu1, Wi1, Wu2, Wi2, Wp1, Wp2, Wt1, Wo};
    int Ks[8]  = {484, 484, 128, 128, 128, 128, 228, 256};
    int Kps[8] = {512, 512, 128, 128, 128, 128, 256, 256};
    int Bs[8]  = {PB_U1, PB_I1, PB_U2, PB_I2, PB_P1, PB_P2, PB_T1, PB_O};
    int cum = 0;
    for (int i = 0; i < 8; i++) {
        pa.W[i] = Ws[i]; pa.K[i] = Ks[i]; pa.Kp[i] = Kps[i]; pa.base[i] = Bs[i];
        pa.cum[i] = cum; cum += Kps[i];
    }
    pa.cum[8] = cum;
    prep_all_kernel<<<cum, 128>>>(pa);

    // (2,3) winner calc on side stream
    win_init_kernel<<<(nodes + 255) / 256, 256, 0, s2>>>(nodes);
    win_mark_kernel<<<(2 * Bn + 255) / 256, 256, 0, s2>>>(src_ids, dst_ids, Bn);
    cudaEventRecord(evMark, s2);

    // (4) fused chain
    ChainArgs U, I;
    U.ida = src_ids; U.idb = dst_ids; U.emb = src_emb;
    int ubase[6] = {PB_U1, PB_U2, PB_P1, PB_P2, PB_T1, PB_O};
    int ibase[6] = {PB_I1, PB_I2, PB_P1, PB_P2, PB_T1, PB_O};
    int kps6[6]  = {512, 128, 128, 128, 256, 256};
    for (int s = 0; s < 6; s++) { U.wbase[s] = ubase[s]; I.wbase[s] = ibase[s]; U.kp[s] = I.kp[s] = kps6[s]; }
    U.bias[0] = bu1; U.bias[1] = bu2; U.bias[2] = bp1; U.bias[3] = bp2; U.bias[4] = bt1; U.bias[5] = bo;
    I.bias[0] = bi1; I.bias[1] = bi2; I.bias[2] = bp1; I.bias[3] = bp2; I.bias[4] = bt1; I.bias[5] = bo;
    U.ut = ut; U.outp = out;
    I.ida = dst_ids; I.idb = src_ids; I.emb = dst_emb;
    I.ut = it; I.outp = out + (size_t)Bn * MEMD;

    dim3 grid(Bn / MROWS, 2);
    chain_kernel<<<grid, CT, SMEM_DYN>>>(U, I, memory, edge, ts, tw, tb);

    // (5) bulk copy on side stream (after win_mark)
    if (hasMem) {
        copy_pass_kernel<<<COPY_BLOCKS, 128, 0, s2>>>(
            (const float4*)memory, (float4*)out_mem, nodes);
    }
    cudaEventRecord(evCopy, s2);

    // (6) winner scatter after chain + winner calc
    if (hasMem) {
        cudaStreamWaitEvent(0, evMark, 0);
        scatter_win_kernel<<<2 * Bn, 128>>>(src_ids, dst_ids, ut, it, out_mem, Bn);
    }
    cudaStreamWaitEvent(0, evCopy, 0);
}